// round 5
// baseline (speedup 1.0000x reference)
#include <cuda_runtime.h>

// HungarianMatcher cost matrix: C[bs,nq,nt] =
//   5*L1(cxcywh) + 2*focal_class_cost(gathered by tgt_id) - 2*GIoU(xyxy)
//
// R4 changes vs R3 (instruction-count round; alu/FMNMX reduction):
//  - intersection width via enclosing-box identity:
//      min(a,b) = a+b-max(a,b)  =>  w = max(0, qw+tw-ex)
//    drops 4 FMNMX/pair (alu pipe, previously the hottest at 42%).
//  - giou = iou - 1 + uni/ae; the "+2" constant folded into the class table;
//    epilogue is a pure RCP+FMUL+FFMA chain.
//  - per-box (area, w, h) precomputed in prep; everything else unchanged.

namespace {
constexpr int BS = 16, NQ = 900, NC = 91, NT = 1600;
constexpr int NROWS = BS * NQ;     // 14400
constexpr int TI = 10;             // query rows per block
constexpr int TPB = 160;           // 5 warps
constexpr int TGT_PER_BLK = 2 * TPB;       // 320
constexpr int NTILE_T = NT / TGT_PER_BLK;  // 5
}

__device__ float  g_cls2[NROWS * NC];   // 2*cost_class + 2
__device__ float4 g_qxyxy[NROWS];
__device__ float4 g_qd[NROWS];          // (area, w, h, 0)
__device__ float4 g_txyxy[NT];
__device__ float4 g_td[NT];             // (area, w, h, 0)
__device__ int    g_tid[NT];

// Fused prep: class table (+2 fold) + box xyxy/area/wh + id decode.
// tgt_ids is int64 in the reference; jax with x64 disabled materializes
// int32. Detect: for nonneg int64 < 2^31, every odd int32 word is 0.
// All detection reads stay within the int32 buffer size.
__global__ void prep_all(const float* __restrict__ logits,
                         const float* __restrict__ pred_boxes,
                         const float* __restrict__ tgt_boxes,
                         const int*   __restrict__ ids32) {
    int i = blockIdx.x * blockDim.x + threadIdx.x;
    if (i < NROWS * NC) {
        float x = logits[i];
        float p = __fdividef(1.0f, 1.0f + __expf(-x));
        float omp = 1.0f - p;
        float pos = 0.25f * omp * omp * (-__logf(p + 1e-8f));
        float neg = 0.75f * p * p * (-__logf(omp + 1e-8f));
        g_cls2[i] = 2.0f * (pos - neg) + 2.0f;   // +2 from -2*giou's (-1) term
    }
    if (i < NROWS + NT) {
        if (i < NROWS) {
            float4 b = reinterpret_cast<const float4*>(pred_boxes)[i];
            float4 xy;
            xy.x = b.x - 0.5f * b.z; xy.y = b.y - 0.5f * b.w;
            xy.z = b.x + 0.5f * b.z; xy.w = b.y + 0.5f * b.w;
            g_qxyxy[i] = xy;
            float w = xy.z - xy.x, h = xy.w - xy.y;
            g_qd[i] = make_float4(w * h, w, h, 0.0f);
        } else {
            int j = i - NROWS;
            float4 b = reinterpret_cast<const float4*>(tgt_boxes)[j];
            float4 xy;
            xy.x = b.x - 0.5f * b.z; xy.y = b.y - 0.5f * b.w;
            xy.z = b.x + 0.5f * b.z; xy.w = b.y + 0.5f * b.w;
            g_txyxy[j] = xy;
            float w = xy.z - xy.x, h = xy.w - xy.y;
            g_td[j] = make_float4(w * h, w, h, 0.0f);
        }
    }
    if (i < NT) {
        bool is64 = true;
#pragma unroll
        for (int k = 1; k < 128; k += 2)
            is64 &= (ids32[k] == 0);
        g_tid[i] = is64 ? ids32[2 * i] : ids32[i];
    }
}

__device__ __forceinline__ float pair_cost(
    const float4 qxy, const float4 qc, const float4 qd,
    const float4 txy, const float4 tc, const float4 td,
    const float cls2p)
{
    // L1 on cxcywh (fma pipe; abs folded into operand modifiers)
    float bb = fabsf(qc.x - tc.x) + fabsf(qc.y - tc.y)
             + fabsf(qc.z - tc.z) + fabsf(qc.w - tc.w);
    // enclosing box first; intersection derived from it:
    //   min(q2,t2) - max(q1,t1) = (qw + tw) - ex
    float ex = fmaxf(qxy.z, txy.z) - fminf(qxy.x, txy.x);
    float ey = fmaxf(qxy.w, txy.w) - fminf(qxy.y, txy.y);
    float w  = fmaxf((qd.y + td.y) - ex, 0.0f);
    float h  = fmaxf((qd.z + td.z) - ey, 0.0f);
    float inter = w * h;
    float uni = (qd.x + td.x) - inter;
    float ae  = ex * ey;
    // C = 5*bb + (2*cls+2) - 2*inter/uni - 2*uni/ae
    float c = fmaf(5.0f, bb, cls2p);
    c = fmaf(-2.0f * inter, __fdividef(1.0f, uni), c);
    c = fmaf(-2.0f * uni,   __fdividef(1.0f, ae),  c);
    return c;
}

__global__ void __launch_bounds__(TPB, 8)
cost_kernel(const float* __restrict__ pred_boxes,
            const float* __restrict__ tgt_boxes,
            float* __restrict__ out)
{
    __shared__ float  s_cls[TI * NC];   // 3.6 KB
    __shared__ float4 s_qxy[TI];
    __shared__ float4 s_qc[TI];
    __shared__ float4 s_qd[TI];

    const int t  = threadIdx.x;
    const int r0 = blockIdx.x * TI;
    const int j0 = blockIdx.y * TGT_PER_BLK + 2 * t;

    for (int k = t; k < TI * NC; k += TPB)
        s_cls[k] = g_cls2[r0 * NC + k];
    if (t < TI) {
        s_qxy[t] = g_qxyxy[r0 + t];
        s_qc[t]  = reinterpret_cast<const float4*>(pred_boxes)[r0 + t];
        s_qd[t]  = g_qd[r0 + t];
    }

    // per-thread target constants (registers)
    const float4 t0xy = g_txyxy[j0];
    const float4 t1xy = g_txyxy[j0 + 1];
    const float4 t0d  = g_td[j0];
    const float4 t1d  = g_td[j0 + 1];
    const float4 t0c  = reinterpret_cast<const float4*>(tgt_boxes)[j0];
    const float4 t1c  = reinterpret_cast<const float4*>(tgt_boxes)[j0 + 1];
    const int id0 = g_tid[j0];
    const int id1 = g_tid[j0 + 1];
    __syncthreads();

    float* orow = out + (size_t)r0 * NT + j0;

#pragma unroll
    for (int q = 0; q < TI; ++q) {
        const float4 qxy = s_qxy[q];
        const float4 qc  = s_qc[q];
        const float4 qd  = s_qd[q];
        float c0 = pair_cost(qxy, qc, qd, t0xy, t0c, t0d, s_cls[q * NC + id0]);
        float c1 = pair_cost(qxy, qc, qd, t1xy, t1c, t1d, s_cls[q * NC + id1]);
        *reinterpret_cast<float2*>(orow + (size_t)q * NT) = make_float2(c0, c1);
    }
}

extern "C" void kernel_launch(void* const* d_in, const int* in_sizes, int n_in,
                              void* d_out, int out_size) {
    const float* logits = (const float*)d_in[0];   // [16,900,91]
    const float* pboxes = (const float*)d_in[1];   // [16,900,4]
    const float* tboxes = (const float*)d_in[2];   // [1600,4]
    const int*   ids    = (const int*)d_in[3];     // [1600] (int32 or int64 view)
    float* out = (float*)d_out;                    // [16,900,1600]

    prep_all<<<(NROWS * NC + 255) / 256, 256>>>(logits, pboxes, tboxes, ids);
    dim3 grid(NROWS / TI, NTILE_T);
    cost_kernel<<<grid, TPB>>>(pboxes, tboxes, out);
}